// round 1
// baseline (speedup 1.0000x reference)
#include <cuda_runtime.h>
#include <cuda_bf16.h>
#include <math.h>

// Fused: h = softplus(x@W1 + b1) - ln2 ; node_out = h@W2 ; out[g] += node_out
//
// Tile: 128 nodes x 128 hidden per block, 256 threads, 8x8 register micro-tile.
// W1 (128x128 fp32 = 64KB) fully staged in dynamic smem per block.
// x staged in K-chunks of 16, transposed with pad-129 stride (conflict-free).

#define TN 128          // nodes per block
#define KC 16           // k chunk
#define XS_STRIDE 129   // padded stride for transposed x tile
#define NTHREADS 256

#define W1_ELEMS (128 * 128)
#define XS_ELEMS (KC * XS_STRIDE)
#define SMEM_BYTES ((W1_ELEMS + XS_ELEMS) * sizeof(float))

__device__ __forceinline__ float shifted_softplus(float z) {
    // log1p(exp(z)) computed stably, minus ln(2)
    return fmaxf(z, 0.0f) + log1pf(expf(-fabsf(z))) - 0.69314718055994531f;
}

__global__ void __launch_bounds__(NTHREADS, 2)
fused_mlp_segsum(const float* __restrict__ x,
                 const float* __restrict__ W1,
                 const float* __restrict__ b1,
                 const float* __restrict__ W2,
                 const int*   __restrict__ batch,
                 float* __restrict__ out,
                 int n_nodes)
{
    extern __shared__ float smem[];
    float* w1s = smem;              // [128][128] row = k, col = j
    float* xs  = smem + W1_ELEMS;   // [KC][XS_STRIDE] row = kk, col = node

    __shared__ float w2s[128];
    __shared__ float b1s[128];
    __shared__ float nodeacc[TN];

    const int tid = threadIdx.x;
    const long base = (long)blockIdx.x * TN;

    // Stage full W1 (vectorized, coalesced)
    #pragma unroll
    for (int i = tid; i < W1_ELEMS / 4; i += NTHREADS) {
        ((float4*)w1s)[i] = ((const float4*)W1)[i];
    }
    if (tid < 128) {
        w2s[tid] = W2[tid];
        b1s[tid] = b1[tid];
        nodeacc[tid] = 0.0f;
    }

    const int tx = tid & 15;   // hidden group (8 cols each)
    const int ty = tid >> 4;   // node group  (8 rows each)
    const int node0 = ty * 8;
    const int j0 = tx * 8;

    float acc[8][8];
    #pragma unroll
    for (int i = 0; i < 8; i++)
        #pragma unroll
        for (int j = 0; j < 8; j++) acc[i][j] = 0.0f;

    for (int k0 = 0; k0 < 128; k0 += KC) {
        __syncthreads();
        // Stage x chunk, transposed: xs[kk][node] = x[base+node][k0+kk]
        // Consecutive tids read consecutive k within a node row -> coalesced.
        #pragma unroll
        for (int r = 0; r < (TN * KC) / NTHREADS; r++) {
            int flat = r * NTHREADS + tid;
            int node = flat >> 4;     // /KC
            int kk   = flat & 15;     // %KC
            long gnode = base + node;
            float v = 0.0f;
            if (gnode < n_nodes) v = x[gnode * 128 + (k0 + kk)];
            xs[kk * XS_STRIDE + node] = v;
        }
        __syncthreads();

        #pragma unroll
        for (int kk = 0; kk < KC; kk++) {
            float xv[8];
            #pragma unroll
            for (int i = 0; i < 8; i++)
                xv[i] = xs[kk * XS_STRIDE + node0 + i];
            // vectorized W row load (32B-aligned, conflict-free/broadcast)
            float4 wlo = *(const float4*)&w1s[(k0 + kk) * 128 + j0];
            float4 whi = *(const float4*)&w1s[(k0 + kk) * 128 + j0 + 4];
            float wv[8] = {wlo.x, wlo.y, wlo.z, wlo.w, whi.x, whi.y, whi.z, whi.w};
            #pragma unroll
            for (int i = 0; i < 8; i++)
                #pragma unroll
                for (int j = 0; j < 8; j++)
                    acc[i][j] = fmaf(xv[i], wv[j], acc[i][j]);
        }
    }

    // Epilogue: bias + shifted softplus + dot with W2 (partial over our 8 hidden)
    __syncthreads();   // nodeacc zeroed above; all k-loop smem use done

    float lw2[8], lb[8];
    #pragma unroll
    for (int j = 0; j < 8; j++) { lw2[j] = w2s[j0 + j]; lb[j] = b1s[j0 + j]; }

    #pragma unroll
    for (int i = 0; i < 8; i++) {
        float s = 0.0f;
        #pragma unroll
        for (int j = 0; j < 8; j++) {
            float z = acc[i][j] + lb[j];
            s = fmaf(shifted_softplus(z), lw2[j], s);
        }
        atomicAdd(&nodeacc[node0 + i], s);  // 16 partials per node (smem)
    }
    __syncthreads();

    // Scatter into per-graph output
    if (tid < TN) {
        long gnode = base + tid;
        if (gnode < n_nodes) {
            int g = batch[gnode];
            atomicAdd(&out[g], nodeacc[tid]);
        }
    }
}

__global__ void zero_out_kernel(float* out, int n) {
    int i = blockIdx.x * blockDim.x + threadIdx.x;
    if (i < n) out[i] = 0.0f;
}

extern "C" void kernel_launch(void* const* d_in, const int* in_sizes, int n_in,
                              void* d_out, int out_size)
{
    const float* x     = (const float*)d_in[0];
    const float* W1    = (const float*)d_in[1];
    const float* b1    = (const float*)d_in[2];
    const float* W2    = (const float*)d_in[3];
    const int*   batch = (const int*)d_in[4];
    float* out = (float*)d_out;

    const int n_nodes = in_sizes[0] / 128;

    // Output is poisoned; zero it (graph-capturable kernel launch).
    zero_out_kernel<<<(out_size + 255) / 256, 256>>>(out, out_size);

    static bool attr_set = false;
    if (!attr_set) {
        cudaFuncSetAttribute(fused_mlp_segsum,
                             cudaFuncAttributeMaxDynamicSharedMemorySize,
                             (int)SMEM_BYTES);
        attr_set = true;
    }

    int grid = (n_nodes + TN - 1) / TN;
    fused_mlp_segsum<<<grid, NTHREADS, SMEM_BYTES>>>(x, W1, b1, W2, batch, out, n_nodes);
}

// round 2
// speedup vs baseline: 1.0725x; 1.0725x over previous
#include <cuda_runtime.h>
#include <cuda_bf16.h>
#include <math.h>

// Fused: h = softplus(x@W1 + b1) - ln2 ; node_out = h@W2 ; out[g] += node_out
//
// Round 2: packed f32x2 FFMA (fma.rn.f32x2) — 2 FMAs/issue on the fma pipe.
// Tile: 128 nodes x 128 hidden per block, 256 threads, 8x(4x2) register micro-tile.
// W1 (128x128 fp32 = 64KB) fully staged in dynamic smem per block.
// x staged in K-chunks of 16, transposed with pad-132 stride (conflict-free,
// 16B-aligned so node-dim reads vectorize to LDS.128).

#define TN 128          // nodes per block
#define KC 16           // k chunk
#define XS_STRIDE 132   // padded stride: (kk*33)%32 permutes banks; 132*4%16==0
#define NTHREADS 256

#define W1_ELEMS (128 * 128)
#define XS_ELEMS (KC * XS_STRIDE)
#define SMEM_BYTES ((W1_ELEMS + XS_ELEMS) * sizeof(float))

typedef unsigned long long u64;

__device__ __forceinline__ void ffma2(u64& d, u64 a, u64 b) {
    // packed: d.lo += a.lo*b.lo ; d.hi += a.hi*b.hi
    asm("fma.rn.f32x2 %0, %1, %2, %0;" : "+l"(d) : "l"(a), "l"(b));
}

__device__ __forceinline__ u64 dup2(float v) {
    u64 r;
    asm("mov.b64 %0, {%1, %1};" : "=l"(r) : "f"(v));
    return r;
}

__device__ __forceinline__ void unpack2(u64 v, float& lo, float& hi) {
    asm("mov.b64 {%0, %1}, %2;" : "=f"(lo), "=f"(hi) : "l"(v));
}

__device__ __forceinline__ float shifted_softplus(float z) {
    return fmaxf(z, 0.0f) + log1pf(expf(-fabsf(z))) - 0.69314718055994531f;
}

__global__ void __launch_bounds__(NTHREADS, 2)
fused_mlp_segsum(const float* __restrict__ x,
                 const float* __restrict__ W1,
                 const float* __restrict__ b1,
                 const float* __restrict__ W2,
                 const int*   __restrict__ batch,
                 float* __restrict__ out,
                 int n_nodes)
{
    extern __shared__ float smem[];
    float* w1s = smem;              // [128][128] row = k, col = j
    float* xs  = smem + W1_ELEMS;   // [KC][XS_STRIDE] row = kk, col = node

    __shared__ float w2s[128];
    __shared__ float b1s[128];
    __shared__ float nodeacc[TN];

    const int tid = threadIdx.x;
    const long base = (long)blockIdx.x * TN;

    // Stage full W1 (vectorized, coalesced)
    #pragma unroll
    for (int i = tid; i < W1_ELEMS / 4; i += NTHREADS) {
        ((float4*)w1s)[i] = ((const float4*)W1)[i];
    }
    if (tid < 128) {
        w2s[tid] = W2[tid];
        b1s[tid] = b1[tid];
        nodeacc[tid] = 0.0f;
    }

    const int tx = tid & 15;   // hidden group (8 cols each)
    const int ty = tid >> 4;   // node group  (8 rows each)
    const int node0 = ty * 8;
    const int j0 = tx * 8;

    // acc2[i][j2] packs hidden pair (j0+2*j2, j0+2*j2+1) for node (node0+i)
    u64 acc2[8][4];
    #pragma unroll
    for (int i = 0; i < 8; i++)
        #pragma unroll
        for (int j = 0; j < 4; j++) acc2[i][j] = 0ull;

    for (int k0 = 0; k0 < 128; k0 += KC) {
        __syncthreads();
        // Stage x chunk, transposed: xs[kk][node] = x[base+node][k0+kk]
        #pragma unroll
        for (int r = 0; r < (TN * KC) / NTHREADS; r++) {
            int flat = r * NTHREADS + tid;
            int node = flat >> 4;     // /KC
            int kk   = flat & 15;     // %KC
            long gnode = base + node;
            float v = 0.0f;
            if (gnode < n_nodes) v = x[gnode * 128 + (k0 + kk)];
            xs[kk * XS_STRIDE + node] = v;
        }
        __syncthreads();

        #pragma unroll
        for (int kk = 0; kk < KC; kk++) {
            // x values for our 8 nodes: two LDS.128
            float4 xa = *(const float4*)&xs[kk * XS_STRIDE + node0];
            float4 xb = *(const float4*)&xs[kk * XS_STRIDE + node0 + 4];
            u64 xx[8];
            xx[0] = dup2(xa.x); xx[1] = dup2(xa.y);
            xx[2] = dup2(xa.z); xx[3] = dup2(xa.w);
            xx[4] = dup2(xb.x); xx[5] = dup2(xb.y);
            xx[6] = dup2(xb.z); xx[7] = dup2(xb.w);

            // W row pairs: adjacent floats form the packed u64 directly
            ulonglong2 wq0 = *(const ulonglong2*)&w1s[(k0 + kk) * 128 + j0];
            ulonglong2 wq1 = *(const ulonglong2*)&w1s[(k0 + kk) * 128 + j0 + 4];
            u64 wv[4] = {wq0.x, wq0.y, wq1.x, wq1.y};

            #pragma unroll
            for (int i = 0; i < 8; i++) {
                ffma2(acc2[i][0], xx[i], wv[0]);
                ffma2(acc2[i][1], xx[i], wv[1]);
                ffma2(acc2[i][2], xx[i], wv[2]);
                ffma2(acc2[i][3], xx[i], wv[3]);
            }
        }
    }

    // Epilogue: bias + shifted softplus + dot with W2 (partial over our 8 hidden)
    __syncthreads();   // nodeacc zeroed above; all k-loop smem use done

    float lw2[8], lb[8];
    #pragma unroll
    for (int j = 0; j < 8; j++) { lw2[j] = w2s[j0 + j]; lb[j] = b1s[j0 + j]; }

    #pragma unroll
    for (int i = 0; i < 8; i++) {
        float s = 0.0f;
        #pragma unroll
        for (int j2 = 0; j2 < 4; j2++) {
            float alo, ahi;
            unpack2(acc2[i][j2], alo, ahi);
            float zlo = alo + lb[2 * j2];
            float zhi = ahi + lb[2 * j2 + 1];
            s = fmaf(shifted_softplus(zlo), lw2[2 * j2], s);
            s = fmaf(shifted_softplus(zhi), lw2[2 * j2 + 1], s);
        }
        atomicAdd(&nodeacc[node0 + i], s);  // 16 partials per node (smem)
    }
    __syncthreads();

    // Scatter into per-graph output
    if (tid < TN) {
        long gnode = base + tid;
        if (gnode < n_nodes) {
            int g = batch[gnode];
            atomicAdd(&out[g], nodeacc[tid]);
        }
    }
}

__global__ void zero_out_kernel(float* out, int n) {
    int i = blockIdx.x * blockDim.x + threadIdx.x;
    if (i < n) out[i] = 0.0f;
}

extern "C" void kernel_launch(void* const* d_in, const int* in_sizes, int n_in,
                              void* d_out, int out_size)
{
    const float* x     = (const float*)d_in[0];
    const float* W1    = (const float*)d_in[1];
    const float* b1    = (const float*)d_in[2];
    const float* W2    = (const float*)d_in[3];
    const int*   batch = (const int*)d_in[4];
    float* out = (float*)d_out;

    const int n_nodes = in_sizes[0] / 128;

    // Output is poisoned; zero it (graph-capturable kernel launch).
    zero_out_kernel<<<(out_size + 255) / 256, 256>>>(out, out_size);

    static bool attr_set = false;
    if (!attr_set) {
        cudaFuncSetAttribute(fused_mlp_segsum,
                             cudaFuncAttributeMaxDynamicSharedMemorySize,
                             (int)SMEM_BYTES);
        attr_set = true;
    }

    int grid = (n_nodes + TN - 1) / TN;
    fused_mlp_segsum<<<grid, NTHREADS, SMEM_BYTES>>>(x, W1, b1, W2, batch, out, n_nodes);
}

// round 4
// speedup vs baseline: 2.9643x; 2.7639x over previous
#include <cuda_runtime.h>
#include <cuda_bf16.h>
#include <cstdint>
#include <math.h>

// ============================================================================
// Fused Node2Prop2 via mma.sync bf16x3 split-precision (base sm_103 target —
// no 'a'-gated features: mma.sync + ldmatrix + cp.async only).
//   H = X@W1 = Xh@Wh + Xh@Wl + Xl@Wh   (bf16 frags, fp32 accum)
//   out[g] += sum_nodes ( softplus(H + b1) - ln2 ) @ W2
// Persistent kernel, double-buffered fp32 x tiles via cp.async; x split to
// bf16 hi/lo in registers at fragment build; W1 pre-split/transposed by prep.
// ============================================================================

#define NTHREADS 256
#define TILE_M   128

// x fp32 smem: row stride 132 floats (528B: 16B-aligned, bank-shifted)
#define XSTRIDE  132
#define XBYTES   (128 * XSTRIDE * 4)          // 67584 per buffer
// W bf16 smem: row j, stride 136 bf16 (272B: 16B-aligned, bank-shifted)
#define WSTRIDE  136
#define WBYTES   (128 * WSTRIDE * 2)          // 34816 per precision
#define OFF_XB0  0
#define OFF_XB1  XBYTES
#define OFF_WH   (2 * XBYTES)
#define OFF_WL   (2 * XBYTES + WBYTES)
#define SMEM_DYN (2 * XBYTES + 2 * WBYTES)    // 204800

#define LOG2E 1.4426950408889634f
#define LN2   0.6931471805599453f

// ---------------- helpers ---------------------------------------------------

__device__ __forceinline__ uint32_t smem_u32(const void* p) {
    uint32_t a;
    asm("{ .reg .u64 t; cvta.to.shared.u64 t, %1; cvt.u32.u64 %0, t; }"
        : "=r"(a) : "l"(p));
    return a;
}

__device__ __forceinline__ float2 lds64(uint32_t a) {
    float2 v;
    asm volatile("ld.shared.v2.f32 {%0, %1}, [%2];"
                 : "=f"(v.x), "=f"(v.y) : "r"(a));
    return v;
}

__device__ __forceinline__ void cp_async16(uint32_t dst, const float* src) {
    asm volatile("cp.async.cg.shared.global [%0], [%1], 16;"
                 :: "r"(dst), "l"(src) : "memory");
}
__device__ __forceinline__ void cp_commit() {
    asm volatile("cp.async.commit_group;" ::: "memory");
}
__device__ __forceinline__ void sts_zero16(uint32_t dst) {
    asm volatile("st.shared.v4.b32 [%0], {%1, %1, %1, %1};"
                 :: "r"(dst), "r"(0) : "memory");
}

__device__ __forceinline__ void ldmatrix_x4(uint32_t& r0, uint32_t& r1,
                                            uint32_t& r2, uint32_t& r3,
                                            uint32_t addr) {
    asm volatile("ldmatrix.sync.aligned.m8n8.x4.shared.b16 {%0,%1,%2,%3}, [%4];"
                 : "=r"(r0), "=r"(r1), "=r"(r2), "=r"(r3) : "r"(addr));
}

__device__ __forceinline__ void mma_bf16(float* d, const uint32_t* a,
                                         uint32_t b0, uint32_t b1) {
    asm volatile(
        "mma.sync.aligned.m16n8k16.row.col.f32.bf16.bf16.f32 "
        "{%0,%1,%2,%3}, {%4,%5,%6,%7}, {%8,%9}, {%0,%1,%2,%3};"
        : "+f"(d[0]), "+f"(d[1]), "+f"(d[2]), "+f"(d[3])
        : "r"(a[0]), "r"(a[1]), "r"(a[2]), "r"(a[3]), "r"(b0), "r"(b1));
}

// pack two fp32 into bf16x2 (lo = first elem), and produce residual pack
__device__ __forceinline__ void split_pair(float2 v, uint32_t& hi, uint32_t& lo) {
    asm("cvt.rn.bf16x2.f32 %0, %1, %2;" : "=r"(hi) : "f"(v.y), "f"(v.x));
    float flo = __uint_as_float(hi << 16);
    float fhi = __uint_as_float(hi & 0xffff0000u);
    float rx = v.x - flo;
    float ry = v.y - fhi;
    asm("cvt.rn.bf16x2.f32 %0, %1, %2;" : "=r"(lo) : "f"(ry), "f"(rx));
}

__device__ __forceinline__ float softplus_lg2(float z) {
    // returns lg2(1 + 2^(z*log2e));  (softplus - ln2) = (this - 1) * ln2
    float w = z * LOG2E;
    float e, l;
    asm("ex2.approx.f32 %0, %1;" : "=f"(e) : "f"(w));
    asm("lg2.approx.f32 %0, %1;" : "=f"(l) : "f"(1.0f + e));
    return l;
}

// ---------------- prepped W1: split + transposed [j][k], padded stride ------

__device__ unsigned short g_wh[128 * WSTRIDE];
__device__ unsigned short g_wl[128 * WSTRIDE];

__global__ void prep_w1(const float* __restrict__ W1) {
    int idx = blockIdx.x * blockDim.x + threadIdx.x;
    if (idx >= 128 * 128) return;
    int j = idx >> 7;          // hidden (row of W^T)
    int k = idx & 127;         // contraction (contiguous)
    float w = W1[k * 128 + j];
    __nv_bfloat16 h = __float2bfloat16_rn(w);
    float hf = __bfloat162float(h);
    __nv_bfloat16 l = __float2bfloat16_rn(w - hf);
    g_wh[j * WSTRIDE + k] = __bfloat16_as_ushort(h);
    g_wl[j * WSTRIDE + k] = __bfloat16_as_ushort(l);
}

__global__ void zero_out_kernel(float* out, int n) {
    int i = blockIdx.x * blockDim.x + threadIdx.x;
    if (i < n) out[i] = 0.0f;
}

// ---------------- main persistent kernel ------------------------------------

__global__ void __launch_bounds__(NTHREADS, 1)
fused_mlp_hmma(const float* __restrict__ x,
               const float* __restrict__ b1,
               const float* __restrict__ W2,
               const int*   __restrict__ batch,
               float* __restrict__ out,
               int n_nodes, int n_tiles)
{
    extern __shared__ char dsm[];
    const uint32_t sbase = smem_u32(dsm);
    const uint32_t xsb[2] = { sbase + OFF_XB0, sbase + OFF_XB1 };
    const uint32_t whb = sbase + OFF_WH;
    const uint32_t wlb = sbase + OFF_WL;

    __shared__ float s_b1[128];
    __shared__ float s_w2[128];        // W2 * ln2
    __shared__ float s_partial[2][128];

    const int tid  = threadIdx.x;
    const int wid  = tid >> 5;
    const int lane = tid & 31;
    const int mgrp = wid & 3;          // 4 m-groups x 32 nodes
    const int ngrp = wid >> 2;         // 2 n-groups x 64 hidden
    const int qr   = lane >> 2;
    const int qc   = lane & 3;

    // ---- prologue: stage W hi/lo to smem, b1/w2 ---------------------------
    {
        const uint4* gh = (const uint4*)g_wh;
        const uint4* gl = (const uint4*)g_wl;
        uint4* sh = (uint4*)(dsm + OFF_WH);
        uint4* sl = (uint4*)(dsm + OFF_WL);
        for (int i = tid; i < WBYTES / 16; i += NTHREADS) {
            sh[i] = gh[i];
            sl[i] = gl[i];
        }
    }
    if (tid < 128) {
        s_b1[tid] = b1[tid];
        s_w2[tid] = W2[tid] * LN2;
    }
    __syncthreads();

    // per-thread constant: sum of w2*ln2 over this thread's 16 columns
    float c0 = 0.0f;
    #pragma unroll
    for (int nt = 0; nt < 8; nt++) {
        int jb = ngrp * 64 + nt * 8 + 2 * qc;
        c0 += s_w2[jb] + s_w2[jb + 1];
    }

    const int G = gridDim.x;
    const int bid = blockIdx.x;
    const int T = (bid < n_tiles) ? ((n_tiles - 1 - bid) / G + 1) : 0;

    // ---- async x tile loader ----------------------------------------------
    auto load_tile = [&](int tile, int buf) {
        const float* src = x + (size_t)tile * TILE_M * 128;
        bool full = ((size_t)(tile + 1)) * TILE_M <= (size_t)n_nodes;
        #pragma unroll
        for (int it = 0; it < 16; it++) {
            int i = it * NTHREADS + tid;
            int row = i >> 5;
            int ch  = i & 31;
            uint32_t dst = xsb[buf] + (uint32_t)(row * (XSTRIDE * 4) + ch * 16);
            if (full || (size_t)tile * TILE_M + row < (size_t)n_nodes)
                cp_async16(dst, src + row * 128 + ch * 4);
            else
                sts_zero16(dst);
        }
        cp_commit();
    };

    // ---- compute one tile --------------------------------------------------
    auto compute_tile = [&](int tile, int buf) {
        float acc[2][8][4];
        #pragma unroll
        for (int mt = 0; mt < 2; mt++)
            #pragma unroll
            for (int nt = 0; nt < 8; nt++)
                #pragma unroll
                for (int e = 0; e < 4; e++) acc[mt][nt][e] = 0.0f;

        const uint32_t xb = xsb[buf];

        #pragma unroll 4
        for (int ks = 0; ks < 8; ks++) {
            const int k0 = ks * 16;
            const int kc = k0 + 2 * qc;

            // A fragments: fp32 from smem, split to bf16 hi/lo in regs
            uint32_t Ah[2][4], Al[2][4];
            #pragma unroll
            for (int mt = 0; mt < 2; mt++) {
                int r = mgrp * 32 + mt * 16 + qr;
                uint32_t b0 = xb + (uint32_t)((r * XSTRIDE + kc) * 4);
                uint32_t b8 = b0 + 8 * XSTRIDE * 4;
                float2 v00 = lds64(b0);
                float2 v10 = lds64(b8);
                float2 v01 = lds64(b0 + 32);
                float2 v11 = lds64(b8 + 32);
                split_pair(v00, Ah[mt][0], Al[mt][0]);
                split_pair(v10, Ah[mt][1], Al[mt][1]);
                split_pair(v01, Ah[mt][2], Al[mt][2]);
                split_pair(v11, Ah[mt][3], Al[mt][3]);
            }

            // B fragments (ldmatrix.x4 covers two n-tiles x 16k) + MMAs
            const uint32_t l8 = lane & 7;
            const uint32_t gsel = lane >> 3;
            #pragma unroll
            for (int ntp = 0; ntp < 4; ntp++) {
                uint32_t jrow = (uint32_t)(ngrp * 64 + ntp * 16) + ((gsel & 1) << 3) + l8;
                uint32_t kcol = (uint32_t)k0 + ((gsel >> 1) << 3);
                uint32_t off  = jrow * (WSTRIDE * 2) + kcol * 2;
                uint32_t h0, h1, h2, h3, l0, l1, l2, l3;
                ldmatrix_x4(h0, h1, h2, h3, whb + off);
                ldmatrix_x4(l0, l1, l2, l3, wlb + off);
                #pragma unroll
                for (int mt = 0; mt < 2; mt++) {
                    mma_bf16(acc[mt][ntp * 2],     Ah[mt], h0, h2);
                    mma_bf16(acc[mt][ntp * 2],     Ah[mt], l0, l2);
                    mma_bf16(acc[mt][ntp * 2],     Al[mt], h0, h2);
                    mma_bf16(acc[mt][ntp * 2 + 1], Ah[mt], h1, h3);
                    mma_bf16(acc[mt][ntp * 2 + 1], Ah[mt], l1, l3);
                    mma_bf16(acc[mt][ntp * 2 + 1], Al[mt], h1, h3);
                }
            }
        }

        // ---- epilogue: softplus + dot W2, lane reduce, node scatter -------
        float p[2][2];
        p[0][0] = p[0][1] = p[1][0] = p[1][1] = -c0;
        #pragma unroll
        for (int mt = 0; mt < 2; mt++) {
            #pragma unroll
            for (int nt = 0; nt < 8; nt++) {
                int jb = ngrp * 64 + nt * 8 + 2 * qc;
                float bx = s_b1[jb], by = s_b1[jb + 1];
                float wx = s_w2[jb], wy = s_w2[jb + 1];
                p[mt][0] = fmaf(softplus_lg2(acc[mt][nt][0] + bx), wx, p[mt][0]);
                p[mt][0] = fmaf(softplus_lg2(acc[mt][nt][1] + by), wy, p[mt][0]);
                p[mt][1] = fmaf(softplus_lg2(acc[mt][nt][2] + bx), wx, p[mt][1]);
                p[mt][1] = fmaf(softplus_lg2(acc[mt][nt][3] + by), wy, p[mt][1]);
            }
        }
        #pragma unroll
        for (int mt = 0; mt < 2; mt++)
            #pragma unroll
            for (int rr = 0; rr < 2; rr++) {
                p[mt][rr] += __shfl_xor_sync(0xffffffffu, p[mt][rr], 1);
                p[mt][rr] += __shfl_xor_sync(0xffffffffu, p[mt][rr], 2);
            }
        if (qc == 0) {
            int nb = mgrp * 32;
            s_partial[ngrp][nb + qr]      = p[0][0];
            s_partial[ngrp][nb + qr + 8]  = p[0][1];
            s_partial[ngrp][nb + qr + 16] = p[1][0];
            s_partial[ngrp][nb + qr + 24] = p[1][1];
        }
        __syncthreads();
        if (tid < 128) {
            long gn = (long)tile * TILE_M + tid;
            if (gn < n_nodes) {
                float v = s_partial[0][tid] + s_partial[1][tid];
                atomicAdd(&out[batch[gn]], v);
            }
        }
    };

    // ---- pipeline ----------------------------------------------------------
    if (T > 0) {
        load_tile(bid, 0);
        for (int i = 0; i < T; i++) {
            if (i + 1 < T) {
                load_tile(bid + (i + 1) * G, (i + 1) & 1);
                asm volatile("cp.async.wait_group 1;" ::: "memory");
            } else {
                asm volatile("cp.async.wait_group 0;" ::: "memory");
            }
            __syncthreads();
            compute_tile(bid + i * G, i & 1);
        }
    }
}

// ---------------- launch -----------------------------------------------------

extern "C" void kernel_launch(void* const* d_in, const int* in_sizes, int n_in,
                              void* d_out, int out_size)
{
    const float* x     = (const float*)d_in[0];
    const float* W1    = (const float*)d_in[1];
    const float* b1    = (const float*)d_in[2];
    const float* W2    = (const float*)d_in[3];
    const int*   batch = (const int*)d_in[4];
    float* out = (float*)d_out;

    const int n_nodes = in_sizes[0] / 128;
    const int n_tiles = (n_nodes + TILE_M - 1) / TILE_M;

    zero_out_kernel<<<(out_size + 255) / 256, 256>>>(out, out_size);
    prep_w1<<<64, 256>>>(W1);

    cudaFuncSetAttribute(fused_mlp_hmma,
                         cudaFuncAttributeMaxDynamicSharedMemorySize, SMEM_DYN);

    int sms = 148;
    cudaDeviceGetAttribute(&sms, cudaDevAttrMultiProcessorCount, 0);
    int grid = (n_tiles < sms) ? n_tiles : sms;

    fused_mlp_hmma<<<grid, NTHREADS, SMEM_DYN>>>(x, b1, W2, batch, out,
                                                 n_nodes, n_tiles);
}

// round 5
// speedup vs baseline: 3.6151x; 1.2196x over previous
#include <cuda_runtime.h>
#include <cuda_bf16.h>
#include <cuda_fp16.h>
#include <cstdint>
#include <math.h>

// ============================================================================
// Fused Node2Prop2 via mma.sync fp16 2-term split (base sm_103 target).
//   H = X @ fp16(W1) = Xh@Wh + Xl@Wh   (fp16 frags, fp32 accum; error = X@Wl
//   from W1's fp16 rounding only, ~3e-4 rel — under the 1e-3 budget)
//   out[g] += sum_nodes ( softplus(H + b1) - ln2 ) @ W2
// Persistent kernel, double-buffered fp32 x tiles via cp.async; x split to
// fp16 hi/lo in registers at fragment build; W1 pre-converted/transposed.
// ============================================================================

#define NTHREADS 256
#define TILE_M   128

// x fp32 smem: row stride 132 floats (528B: 16B-aligned, bank-shifted)
#define XSTRIDE  132
#define XBYTES   (128 * XSTRIDE * 4)          // 67584 per buffer
// W fp16 smem: row j, stride 136 halves (272B: 16B-aligned, bank-shifted)
#define WSTRIDE  136
#define WBYTES   (128 * WSTRIDE * 2)          // 34816
#define OFF_XB0  0
#define OFF_XB1  XBYTES
#define OFF_WH   (2 * XBYTES)
#define SMEM_DYN (2 * XBYTES + WBYTES)        // 169984

#define LOG2E 1.4426950408889634f
#define LN2   0.6931471805599453f

// ---------------- helpers ---------------------------------------------------

__device__ __forceinline__ uint32_t smem_u32(const void* p) {
    uint32_t a;
    asm("{ .reg .u64 t; cvta.to.shared.u64 t, %1; cvt.u32.u64 %0, t; }"
        : "=r"(a) : "l"(p));
    return a;
}

__device__ __forceinline__ float2 lds64(uint32_t a) {
    float2 v;
    asm volatile("ld.shared.v2.f32 {%0, %1}, [%2];"
                 : "=f"(v.x), "=f"(v.y) : "r"(a));
    return v;
}

__device__ __forceinline__ void cp_async16(uint32_t dst, const float* src) {
    asm volatile("cp.async.cg.shared.global [%0], [%1], 16;"
                 :: "r"(dst), "l"(src) : "memory");
}
__device__ __forceinline__ void cp_commit() {
    asm volatile("cp.async.commit_group;" ::: "memory");
}
__device__ __forceinline__ void sts_zero16(uint32_t dst) {
    asm volatile("st.shared.v4.b32 [%0], {%1, %1, %1, %1};"
                 :: "r"(dst), "r"(0) : "memory");
}

__device__ __forceinline__ void ldmatrix_x4(uint32_t& r0, uint32_t& r1,
                                            uint32_t& r2, uint32_t& r3,
                                            uint32_t addr) {
    asm volatile("ldmatrix.sync.aligned.m8n8.x4.shared.b16 {%0,%1,%2,%3}, [%4];"
                 : "=r"(r0), "=r"(r1), "=r"(r2), "=r"(r3) : "r"(addr));
}

__device__ __forceinline__ void mma_f16(float* d, const uint32_t* a,
                                        uint32_t b0, uint32_t b1) {
    asm volatile(
        "mma.sync.aligned.m16n8k16.row.col.f32.f16.f16.f32 "
        "{%0,%1,%2,%3}, {%4,%5,%6,%7}, {%8,%9}, {%0,%1,%2,%3};"
        : "+f"(d[0]), "+f"(d[1]), "+f"(d[2]), "+f"(d[3])
        : "r"(a[0]), "r"(a[1]), "r"(a[2]), "r"(a[3]), "r"(b0), "r"(b1));
}

// pack two fp32 into f16x2 (lo = first elem), and produce the fp16 residual pack
__device__ __forceinline__ void split_pair(float2 v, uint32_t& hi, uint32_t& lo) {
    asm("cvt.rn.f16x2.f32 %0, %1, %2;" : "=r"(hi) : "f"(v.y), "f"(v.x));
    float fx, fy;
    asm("{ .reg .b16 a, b; mov.b32 {a, b}, %2;"
        " cvt.f32.f16 %0, a; cvt.f32.f16 %1, b; }"
        : "=f"(fx), "=f"(fy) : "r"(hi));
    asm("cvt.rn.f16x2.f32 %0, %1, %2;" : "=r"(lo) : "f"(v.y - fy), "f"(v.x - fx));
}

__device__ __forceinline__ float softplus_lg2(float z) {
    // returns lg2(1 + 2^(z*log2e));  (softplus - ln2) = (this - 1) * ln2
    float w = z * LOG2E;
    float e, l;
    asm("ex2.approx.f32 %0, %1;" : "=f"(e) : "f"(w));
    asm("lg2.approx.f32 %0, %1;" : "=f"(l) : "f"(1.0f + e));
    return l;
}

// ---------------- prepped W1: fp16, transposed [j][k], padded stride --------

__device__ unsigned short g_wh[128 * WSTRIDE];

__global__ void prep_w1(const float* __restrict__ W1, float* __restrict__ out,
                        int out_n) {
    int idx = blockIdx.x * blockDim.x + threadIdx.x;
    if (idx < 128 * 128) {
        int j = idx >> 7;          // hidden (row of W^T)
        int k = idx & 127;         // contraction (contiguous)
        __half h = __float2half_rn(W1[k * 128 + j]);
        g_wh[j * WSTRIDE + k] = __half_as_ushort(h);
    }
    if (idx < out_n) out[idx] = 0.0f;
}

// ---------------- main persistent kernel ------------------------------------

__global__ void __launch_bounds__(NTHREADS, 1)
fused_mlp_hmma(const float* __restrict__ x,
               const float* __restrict__ b1,
               const float* __restrict__ W2,
               const int*   __restrict__ batch,
               float* __restrict__ out,
               int n_nodes, int n_tiles)
{
    extern __shared__ char dsm[];
    const uint32_t sbase = smem_u32(dsm);
    const uint32_t xsb[2] = { sbase + OFF_XB0, sbase + OFF_XB1 };
    const uint32_t whb = sbase + OFF_WH;

    __shared__ float s_b1[128];
    __shared__ float s_w2[128];        // W2 * ln2
    __shared__ float s_partial[2][128];

    const int tid  = threadIdx.x;
    const int wid  = tid >> 5;
    const int lane = tid & 31;
    const int mgrp = wid & 3;          // 4 m-groups x 32 nodes
    const int ngrp = wid >> 2;         // 2 n-groups x 64 hidden
    const int qr   = lane >> 2;
    const int qc   = lane & 3;

    // ---- prologue: stage W to smem, b1/w2 ---------------------------------
    {
        const uint4* gh = (const uint4*)g_wh;
        uint4* sh = (uint4*)(dsm + OFF_WH);
        for (int i = tid; i < WBYTES / 16; i += NTHREADS)
            sh[i] = gh[i];
    }
    if (tid < 128) {
        s_b1[tid] = b1[tid];
        s_w2[tid] = W2[tid] * LN2;
    }
    __syncthreads();

    // per-thread constant: sum of w2*ln2 over this thread's 16 columns
    float c0 = 0.0f;
    #pragma unroll
    for (int nt = 0; nt < 8; nt++) {
        int jb = ngrp * 64 + nt * 8 + 2 * qc;
        c0 += s_w2[jb] + s_w2[jb + 1];
    }

    const int G = gridDim.x;
    const int bid = blockIdx.x;
    const int T = (bid < n_tiles) ? ((n_tiles - 1 - bid) / G + 1) : 0;

    // ---- async x tile loader ----------------------------------------------
    auto load_tile = [&](int tile, int buf) {
        const float* src = x + (size_t)tile * TILE_M * 128;
        bool full = ((size_t)(tile + 1)) * TILE_M <= (size_t)n_nodes;
        #pragma unroll
        for (int it = 0; it < 16; it++) {
            int i = it * NTHREADS + tid;
            int row = i >> 5;
            int ch  = i & 31;
            uint32_t dst = xsb[buf] + (uint32_t)(row * (XSTRIDE * 4) + ch * 16);
            if (full || (size_t)tile * TILE_M + row < (size_t)n_nodes)
                cp_async16(dst, src + row * 128 + ch * 4);
            else
                sts_zero16(dst);
        }
        cp_commit();
    };

    // ---- compute one tile --------------------------------------------------
    auto compute_tile = [&](int tile, int buf) {
        float acc[2][8][4];
        #pragma unroll
        for (int mt = 0; mt < 2; mt++)
            #pragma unroll
            for (int nt = 0; nt < 8; nt++)
                #pragma unroll
                for (int e = 0; e < 4; e++) acc[mt][nt][e] = 0.0f;

        const uint32_t xb = xsb[buf];

        #pragma unroll 4
        for (int ks = 0; ks < 8; ks++) {
            const int k0 = ks * 16;
            const int kc = k0 + 2 * qc;

            // A fragments: fp32 from smem, split to fp16 hi/lo in regs
            uint32_t Ah[2][4], Al[2][4];
            #pragma unroll
            for (int mt = 0; mt < 2; mt++) {
                int r = mgrp * 32 + mt * 16 + qr;
                uint32_t b0 = xb + (uint32_t)((r * XSTRIDE + kc) * 4);
                uint32_t b8 = b0 + 8 * XSTRIDE * 4;
                float2 v00 = lds64(b0);
                float2 v10 = lds64(b8);
                float2 v01 = lds64(b0 + 32);
                float2 v11 = lds64(b8 + 32);
                split_pair(v00, Ah[mt][0], Al[mt][0]);
                split_pair(v10, Ah[mt][1], Al[mt][1]);
                split_pair(v01, Ah[mt][2], Al[mt][2]);
                split_pair(v11, Ah[mt][3], Al[mt][3]);
            }

            // B fragments (ldmatrix.x4 covers two n-tiles x 16k) + MMAs
            const uint32_t l8 = lane & 7;
            const uint32_t gsel = lane >> 3;
            #pragma unroll
            for (int ntp = 0; ntp < 4; ntp++) {
                uint32_t jrow = (uint32_t)(ngrp * 64 + ntp * 16) + ((gsel & 1) << 3) + l8;
                uint32_t kcol = (uint32_t)k0 + ((gsel >> 1) << 3);
                uint32_t off  = jrow * (WSTRIDE * 2) + kcol * 2;
                uint32_t h0, h1, h2, h3;
                ldmatrix_x4(h0, h1, h2, h3, whb + off);
                #pragma unroll
                for (int mt = 0; mt < 2; mt++) {
                    mma_f16(acc[mt][ntp * 2],     Ah[mt], h0, h2);
                    mma_f16(acc[mt][ntp * 2],     Al[mt], h0, h2);
                    mma_f16(acc[mt][ntp * 2 + 1], Ah[mt], h1, h3);
                    mma_f16(acc[mt][ntp * 2 + 1], Al[mt], h1, h3);
                }
            }
        }

        // ---- epilogue: softplus + dot W2, lane reduce, node scatter -------
        float p[2][2];
        p[0][0] = p[0][1] = p[1][0] = p[1][1] = -c0;
        #pragma unroll
        for (int mt = 0; mt < 2; mt++) {
            #pragma unroll
            for (int nt = 0; nt < 8; nt++) {
                int jb = ngrp * 64 + nt * 8 + 2 * qc;
                float bx = s_b1[jb], by = s_b1[jb + 1];
                float wx = s_w2[jb], wy = s_w2[jb + 1];
                p[mt][0] = fmaf(softplus_lg2(acc[mt][nt][0] + bx), wx, p[mt][0]);
                p[mt][0] = fmaf(softplus_lg2(acc[mt][nt][1] + by), wy, p[mt][0]);
                p[mt][1] = fmaf(softplus_lg2(acc[mt][nt][2] + bx), wx, p[mt][1]);
                p[mt][1] = fmaf(softplus_lg2(acc[mt][nt][3] + by), wy, p[mt][1]);
            }
        }
        #pragma unroll
        for (int mt = 0; mt < 2; mt++)
            #pragma unroll
            for (int rr = 0; rr < 2; rr++) {
                p[mt][rr] += __shfl_xor_sync(0xffffffffu, p[mt][rr], 1);
                p[mt][rr] += __shfl_xor_sync(0xffffffffu, p[mt][rr], 2);
            }
        if (qc == 0) {
            int nb = mgrp * 32;
            s_partial[ngrp][nb + qr]      = p[0][0];
            s_partial[ngrp][nb + qr + 8]  = p[0][1];
            s_partial[ngrp][nb + qr + 16] = p[1][0];
            s_partial[ngrp][nb + qr + 24] = p[1][1];
        }
        __syncthreads();
        if (tid < 128) {
            long gn = (long)tile * TILE_M + tid;
            if (gn < n_nodes) {
                float v = s_partial[0][tid] + s_partial[1][tid];
                atomicAdd(&out[batch[gn]], v);
            }
        }
    };

    // ---- pipeline ----------------------------------------------------------
    if (T > 0) {
        load_tile(bid, 0);
        for (int i = 0; i < T; i++) {
            if (i + 1 < T) {
                load_tile(bid + (i + 1) * G, (i + 1) & 1);
                asm volatile("cp.async.wait_group 1;" ::: "memory");
            } else {
                asm volatile("cp.async.wait_group 0;" ::: "memory");
            }
            __syncthreads();
            compute_tile(bid + i * G, i & 1);
        }
    }
}

// ---------------- launch -----------------------------------------------------

extern "C" void kernel_launch(void* const* d_in, const int* in_sizes, int n_in,
                              void* d_out, int out_size)
{
    const float* x     = (const float*)d_in[0];
    const float* W1    = (const float*)d_in[1];
    const float* b1    = (const float*)d_in[2];
    const float* W2    = (const float*)d_in[3];
    const int*   batch = (const int*)d_in[4];
    float* out = (float*)d_out;

    const int n_nodes = in_sizes[0] / 128;
    const int n_tiles = (n_nodes + TILE_M - 1) / TILE_M;

    prep_w1<<<64, 256>>>(W1, out, out_size);

    cudaFuncSetAttribute(fused_mlp_hmma,
                         cudaFuncAttributeMaxDynamicSharedMemorySize, SMEM_DYN);

    int sms = 148;
    cudaDeviceGetAttribute(&sms, cudaDevAttrMultiProcessorCount, 0);
    int grid = (n_tiles < sms) ? n_tiles : sms;

    fused_mlp_hmma<<<grid, NTHREADS, SMEM_DYN>>>(x, b1, W2, batch, out,
                                                 n_nodes, n_tiles);
}

// round 6
// speedup vs baseline: 3.8586x; 1.0673x over previous
#include <cuda_runtime.h>
#include <cuda_fp16.h>
#include <cstdint>
#include <math.h>

// ============================================================================
// Fused Node2Prop2, mma.sync fp16 2-term W-split (base sm_103 target).
//   H = X16 @ (Wh + Wl)   where W1 = fp16(W1) + fp16(W1 - fp16(W1)),
//   X16 = fp16(x).  Error = xl @ W1 (~5e-4 rel, under 1e-3).
//   Wl term accumulated in fp16 (its magnitude ~2^-11 of hi term).
//   out[g] += sum_nodes ( softplus(H + b1) - ln2 ) @ W2
// Two independent 4-warp groups per CTA on 64-row tiles (named barriers) so
// one group's MUFU epilogue overlaps the other group's tensor-pipe MMAs.
// ============================================================================

#define NTHREADS 256
#define TILE_M   64          // per-group tile rows

#define XSTRIDE  132         // fp32 floats per row (528B, 16B-aligned, shifted)
#define XB64     (64 * XSTRIDE * 4)           // 33792 per buffer
#define WSTRIDE  136         // halves per row (272B)
#define WBYTES   (128 * WSTRIDE * 2)          // 34816
#define OFF_W    (4 * XB64)                   // after 2 groups x 2 buffers
#define SMEM_DYN (4 * XB64 + 2 * WBYTES)      // 204800

#define LOG2E 1.4426950408889634f
#define LN2   0.6931471805599453f

// ---------------- helpers ---------------------------------------------------

__device__ __forceinline__ uint32_t smem_u32(const void* p) {
    uint32_t a;
    asm("{ .reg .u64 t; cvta.to.shared.u64 t, %1; cvt.u32.u64 %0, t; }"
        : "=r"(a) : "l"(p));
    return a;
}

__device__ __forceinline__ float2 lds64(uint32_t a) {
    float2 v;
    asm volatile("ld.shared.v2.f32 {%0, %1}, [%2];"
                 : "=f"(v.x), "=f"(v.y) : "r"(a));
    return v;
}

__device__ __forceinline__ void cp_async16(uint32_t dst, const float* src) {
    asm volatile("cp.async.cg.shared.global [%0], [%1], 16;"
                 :: "r"(dst), "l"(src) : "memory");
}
__device__ __forceinline__ void cp_commit() {
    asm volatile("cp.async.commit_group;" ::: "memory");
}
__device__ __forceinline__ void sts_zero16(uint32_t dst) {
    asm volatile("st.shared.v4.b32 [%0], {%1, %1, %1, %1};"
                 :: "r"(dst), "r"(0) : "memory");
}

__device__ __forceinline__ void group_bar(int g) {
    asm volatile("bar.sync %0, 128;" :: "r"(g + 1) : "memory");
}

__device__ __forceinline__ void ldmatrix_x4(uint32_t& r0, uint32_t& r1,
                                            uint32_t& r2, uint32_t& r3,
                                            uint32_t addr) {
    asm volatile("ldmatrix.sync.aligned.m8n8.x4.shared.b16 {%0,%1,%2,%3}, [%4];"
                 : "=r"(r0), "=r"(r1), "=r"(r2), "=r"(r3) : "r"(addr));
}

__device__ __forceinline__ void mma_f32acc(float* d, const uint32_t* a,
                                           uint32_t b0, uint32_t b1) {
    asm volatile(
        "mma.sync.aligned.m16n8k16.row.col.f32.f16.f16.f32 "
        "{%0,%1,%2,%3}, {%4,%5,%6,%7}, {%8,%9}, {%0,%1,%2,%3};"
        : "+f"(d[0]), "+f"(d[1]), "+f"(d[2]), "+f"(d[3])
        : "r"(a[0]), "r"(a[1]), "r"(a[2]), "r"(a[3]), "r"(b0), "r"(b1));
}

__device__ __forceinline__ void mma_f16acc(uint32_t* d, const uint32_t* a,
                                           uint32_t b0, uint32_t b1) {
    asm volatile(
        "mma.sync.aligned.m16n8k16.row.col.f16.f16.f16.f16 "
        "{%0,%1}, {%2,%3,%4,%5}, {%6,%7}, {%0,%1};"
        : "+r"(d[0]), "+r"(d[1])
        : "r"(a[0]), "r"(a[1]), "r"(a[2]), "r"(a[3]), "r"(b0), "r"(b1));
}

__device__ __forceinline__ uint32_t pack_f16(float2 v) {
    uint32_t r;
    asm("cvt.rn.f16x2.f32 %0, %1, %2;" : "=r"(r) : "f"(v.y), "f"(v.x));
    return r;
}

__device__ __forceinline__ float2 unpack_f16(uint32_t u) {
    float a, b;
    asm("{ .reg .b16 x, y; mov.b32 {x, y}, %2;"
        " cvt.f32.f16 %0, x; cvt.f32.f16 %1, y; }"
        : "=f"(a), "=f"(b) : "r"(u));
    return make_float2(a, b);
}

__device__ __forceinline__ float softplus_lg2(float z) {
    // lg2(1 + 2^(z*log2e));  (softplus - ln2) = (this - 1) * ln2
    float w = z * LOG2E;
    float e, l;
    asm("ex2.approx.f32 %0, %1;" : "=f"(e) : "f"(w));
    asm("lg2.approx.f32 %0, %1;" : "=f"(l) : "f"(1.0f + e));
    return l;
}

// ---------------- prepped W1: fp16 hi + residual, transposed [j][k] ---------

__device__ unsigned short g_wh[128 * WSTRIDE];
__device__ unsigned short g_wl[128 * WSTRIDE];

__global__ void prep_w1(const float* __restrict__ W1, float* __restrict__ out,
                        int out_n) {
    int idx = blockIdx.x * blockDim.x + threadIdx.x;
    if (idx < 128 * 128) {
        int j = idx >> 7;          // hidden (row of W^T)
        int k = idx & 127;         // contraction (contiguous)
        float w = W1[k * 128 + j];
        __half h = __float2half_rn(w);
        __half l = __float2half_rn(w - __half2float(h));
        g_wh[j * WSTRIDE + k] = __half_as_ushort(h);
        g_wl[j * WSTRIDE + k] = __half_as_ushort(l);
    }
    if (idx < out_n) out[idx] = 0.0f;
}

// ---------------- main persistent kernel ------------------------------------

__global__ void __launch_bounds__(NTHREADS, 1)
fused_mlp_hmma(const float* __restrict__ x,
               const float* __restrict__ b1,
               const float* __restrict__ W2,
               const int*   __restrict__ batch,
               float* __restrict__ out,
               int n_nodes, int n_tiles)
{
    extern __shared__ char dsm[];
    const uint32_t sbase = smem_u32(dsm);
    const uint32_t whb = sbase + OFF_W;
    const uint32_t wlb = whb + WBYTES;

    __shared__ float s_b1[128];
    __shared__ float s_w2[128];              // W2 * ln2
    __shared__ float s_partial[2][2][64];    // [group][ngrp][node]

    const int tid  = threadIdx.x;
    const int wid  = tid >> 5;
    const int lane = tid & 31;
    const int g    = wid >> 2;         // group 0/1
    const int wg   = wid & 3;          // warp-in-group
    const int mgrp = wg & 1;           // 2 m-groups x 32 nodes
    const int ngrp = wg >> 1;          // 2 n-groups x 64 hidden
    const int t128 = tid & 127;        // thread-in-group
    const int qr   = lane >> 2;
    const int qc   = lane & 3;

    const uint32_t xg = sbase + (uint32_t)g * (2 * XB64);

    // ---- prologue: stage W hi/lo to smem, b1/w2 ---------------------------
    {
        const uint4* gh = (const uint4*)g_wh;
        const uint4* gl = (const uint4*)g_wl;
        uint4* sh = (uint4*)(dsm + OFF_W);
        uint4* sl = (uint4*)(dsm + OFF_W + WBYTES);
        for (int i = tid; i < WBYTES / 16; i += NTHREADS) {
            sh[i] = gh[i];
            sl[i] = gl[i];
        }
    }
    if (tid < 128) {
        s_b1[tid] = b1[tid];
        s_w2[tid] = W2[tid] * LN2;
    }
    __syncthreads();

    // per-thread constant: sum of w2*ln2 over this thread's 16 columns
    float c0 = 0.0f;
    #pragma unroll
    for (int nt = 0; nt < 8; nt++) {
        int jb = ngrp * 64 + nt * 8 + 2 * qc;
        c0 += s_w2[jb] + s_w2[jb + 1];
    }

    const int G2 = gridDim.x * 2;
    const int t0 = blockIdx.x * 2 + g;
    const int T = (t0 < n_tiles) ? ((n_tiles - 1 - t0) / G2 + 1) : 0;

    // ---- async x tile loader (64 rows, group-local) ------------------------
    auto load_tile = [&](int tile, int buf) {
        const float* src = x + (size_t)tile * TILE_M * 128;
        bool full = ((size_t)(tile + 1)) * TILE_M <= (size_t)n_nodes;
        #pragma unroll
        for (int it = 0; it < 16; it++) {
            int i = it * 128 + t128;
            int row = i >> 5;
            int ch  = i & 31;
            uint32_t dst = xg + (uint32_t)(buf * XB64 + row * (XSTRIDE * 4) + ch * 16);
            if (full || (size_t)tile * TILE_M + row < (size_t)n_nodes)
                cp_async16(dst, src + row * 128 + ch * 4);
            else
                sts_zero16(dst);
        }
        cp_commit();
    };

    // ---- compute one 64x128 tile ------------------------------------------
    auto compute_tile = [&](int tile, int buf) {
        float acc[2][8][4];
        uint32_t accl[2][16];
        #pragma unroll
        for (int mt = 0; mt < 2; mt++) {
            #pragma unroll
            for (int nt = 0; nt < 8; nt++) {
                #pragma unroll
                for (int e = 0; e < 4; e++) acc[mt][nt][e] = 0.0f;
                accl[mt][nt * 2] = 0u;
                accl[mt][nt * 2 + 1] = 0u;
            }
        }

        const uint32_t xb = xg + (uint32_t)buf * XB64;

        #pragma unroll 4
        for (int ks = 0; ks < 8; ks++) {
            const int k0 = ks * 16;
            const int kc = k0 + 2 * qc;

            // A fragments: fp32 from smem -> fp16 packs (one cvt per pair)
            uint32_t A[2][4];
            #pragma unroll
            for (int mt = 0; mt < 2; mt++) {
                int r = mt * 32 + (mgrp * 16) + qr;   // rows: mgrp picks 16-row
                // NOTE row mapping: warp covers rows {mgrp*16 + [0,16)} U {32 + mgrp*16 + [0,16)}
                uint32_t b0 = xb + (uint32_t)((r * XSTRIDE + kc) * 4);
                A[mt][0] = pack_f16(lds64(b0));
                A[mt][1] = pack_f16(lds64(b0 + 8 * XSTRIDE * 4));
                A[mt][2] = pack_f16(lds64(b0 + 32));
                A[mt][3] = pack_f16(lds64(b0 + 8 * XSTRIDE * 4 + 32));
            }

            // B fragments + MMAs
            const uint32_t l8 = lane & 7;
            const uint32_t gsel = lane >> 3;
            #pragma unroll
            for (int ntp = 0; ntp < 4; ntp++) {
                uint32_t jrow = (uint32_t)(ngrp * 64 + ntp * 16) + ((gsel & 1) << 3) + l8;
                uint32_t kcol = (uint32_t)k0 + ((gsel >> 1) << 3);
                uint32_t off  = jrow * (WSTRIDE * 2) + kcol * 2;
                uint32_t h0, h1, h2, h3, l0, l1, l2, l3;
                ldmatrix_x4(h0, h1, h2, h3, whb + off);
                ldmatrix_x4(l0, l1, l2, l3, wlb + off);
                #pragma unroll
                for (int mt = 0; mt < 2; mt++) {
                    mma_f32acc(acc[mt][ntp * 2],     A[mt], h0, h2);
                    mma_f32acc(acc[mt][ntp * 2 + 1], A[mt], h1, h3);
                    mma_f16acc(&accl[mt][ntp * 4],     A[mt], l0, l2);
                    mma_f16acc(&accl[mt][ntp * 4 + 2], A[mt], l1, l3);
                }
            }
        }

        // ---- epilogue: lo-term merge + softplus + dot W2 ------------------
        float p[2][2];
        p[0][0] = p[0][1] = p[1][0] = p[1][1] = -c0;
        #pragma unroll
        for (int mt = 0; mt < 2; mt++) {
            #pragma unroll
            for (int nt = 0; nt < 8; nt++) {
                int jb = ngrp * 64 + nt * 8 + 2 * qc;
                float bx = s_b1[jb], by = s_b1[jb + 1];
                float wx = s_w2[jb], wy = s_w2[jb + 1];
                float2 lo0 = unpack_f16(accl[mt][nt * 2]);
                float2 lo1 = unpack_f16(accl[mt][nt * 2 + 1]);
                float z0 = acc[mt][nt][0] + lo0.x + bx;
                float z1 = acc[mt][nt][1] + lo0.y + by;
                float z2 = acc[mt][nt][2] + lo1.x + bx;
                float z3 = acc[mt][nt][3] + lo1.y + by;
                p[mt][0] = fmaf(softplus_lg2(z0), wx, p[mt][0]);
                p[mt][0] = fmaf(softplus_lg2(z1), wy, p[mt][0]);
                p[mt][1] = fmaf(softplus_lg2(z2), wx, p[mt][1]);
                p[mt][1] = fmaf(softplus_lg2(z3), wy, p[mt][1]);
            }
        }
        #pragma unroll
        for (int mt = 0; mt < 2; mt++)
            #pragma unroll
            for (int rr = 0; rr < 2; rr++) {
                p[mt][rr] += __shfl_xor_sync(0xffffffffu, p[mt][rr], 1);
                p[mt][rr] += __shfl_xor_sync(0xffffffffu, p[mt][rr], 2);
            }
        if (qc == 0) {
            #pragma unroll
            for (int mt = 0; mt < 2; mt++) {
                int nb = mt * 32 + mgrp * 16;
                s_partial[g][ngrp][nb + qr]     = p[mt][0];
                s_partial[g][ngrp][nb + qr + 8] = p[mt][1];
            }
        }
        group_bar(g);
        if (t128 < 64) {
            long gn = (long)tile * TILE_M + t128;
            if (gn < n_nodes) {
                float v = s_partial[g][0][t128] + s_partial[g][1][t128];
                atomicAdd(&out[batch[gn]], v);
            }
        }
        group_bar(g);   // protects s_partial and the x buffer being reloaded
    };

    // ---- pipeline ----------------------------------------------------------
    if (T > 0) {
        load_tile(t0, 0);
        for (int i = 0; i < T; i++) {
            if (i + 1 < T) {
                load_tile(t0 + (i + 1) * G2, (i + 1) & 1);
                asm volatile("cp.async.wait_group 1;" ::: "memory");
            } else {
                asm volatile("cp.async.wait_group 0;" ::: "memory");
            }
            group_bar(g);
            compute_tile(t0 + i * G2, i & 1);
        }
    }
}

// ---------------- launch -----------------------------------------------------

extern "C" void kernel_launch(void* const* d_in, const int* in_sizes, int n_in,
                              void* d_out, int out_size)
{
    const float* x     = (const float*)d_in[0];
    const float* W1    = (const float*)d_in[1];
    const float* b1    = (const float*)d_in[2];
    const float* W2    = (const float*)d_in[3];
    const int*   batch = (const int*)d_in[4];
    float* out = (float*)d_out;

    const int n_nodes = in_sizes[0] / 128;
    const int n_tiles = (n_nodes + TILE_M - 1) / TILE_M;

    prep_w1<<<64, 256>>>(W1, out, out_size);

    cudaFuncSetAttribute(fused_mlp_hmma,
                         cudaFuncAttributeMaxDynamicSharedMemorySize, SMEM_DYN);

    int sms = 148;
    cudaDeviceGetAttribute(&sms, cudaDevAttrMultiProcessorCount, 0);
    int pairs = (n_tiles + 1) / 2;
    int grid = (pairs < sms) ? pairs : sms;

    fused_mlp_hmma<<<grid, NTHREADS, SMEM_DYN>>>(x, b1, W2, batch, out,
                                                 n_nodes, n_tiles);
}

// round 7
// speedup vs baseline: 4.9986x; 1.2955x over previous
#include <cuda_runtime.h>
#include <cuda_fp16.h>
#include <cstdint>
#include <math.h>

// ============================================================================
// Fused Node2Prop2, mma.sync single-term fp16 (base sm_103 target).
//   H = fp16(X) @ fp16(W1)   (fp32 accum).  Error = Xl@W + X16@Wl ~ 5.7e-4,
//   both components measured separately in rounds 5/6 (5.28e-4, 2.05e-4).
//   out[g] += sum_nodes ( softplus(H + b1) - ln2 ) @ W2
// Two independent 4-warp groups per CTA on 64-row tiles (named barriers) so
// one group's MUFU epilogue overlaps the other group's tensor-pipe MMAs.
// ============================================================================

#define NTHREADS 256
#define TILE_M   64          // per-group tile rows

#define XSTRIDE  132         // fp32 floats per row (528B, 16B-aligned, shifted)
#define XB64     (64 * XSTRIDE * 4)           // 33792 per buffer
#define WSTRIDE  136         // halves per row (272B)
#define WBYTES   (128 * WSTRIDE * 2)          // 34816
#define OFF_W    (4 * XB64)                   // after 2 groups x 2 buffers
#define SMEM_DYN (4 * XB64 + WBYTES)          // 169984

#define LOG2E 1.4426950408889634f
#define LN2   0.6931471805599453f

// ---------------- helpers ---------------------------------------------------

__device__ __forceinline__ uint32_t smem_u32(const void* p) {
    uint32_t a;
    asm("{ .reg .u64 t; cvta.to.shared.u64 t, %1; cvt.u32.u64 %0, t; }"
        : "=r"(a) : "l"(p));
    return a;
}

__device__ __forceinline__ float2 lds64(uint32_t a) {
    float2 v;
    asm volatile("ld.shared.v2.f32 {%0, %1}, [%2];"
                 : "=f"(v.x), "=f"(v.y) : "r"(a));
    return v;
}

__device__ __forceinline__ void cp_async16(uint32_t dst, const float* src) {
    asm volatile("cp.async.cg.shared.global [%0], [%1], 16;"
                 :: "r"(dst), "l"(src) : "memory");
}
__device__ __forceinline__ void cp_commit() {
    asm volatile("cp.async.commit_group;" ::: "memory");
}
__device__ __forceinline__ void sts_zero16(uint32_t dst) {
    asm volatile("st.shared.v4.b32 [%0], {%1, %1, %1, %1};"
                 :: "r"(dst), "r"(0) : "memory");
}

__device__ __forceinline__ void group_bar(int g) {
    asm volatile("bar.sync %0, 128;" :: "r"(g + 1) : "memory");
}

__device__ __forceinline__ void ldmatrix_x4(uint32_t& r0, uint32_t& r1,
                                            uint32_t& r2, uint32_t& r3,
                                            uint32_t addr) {
    asm volatile("ldmatrix.sync.aligned.m8n8.x4.shared.b16 {%0,%1,%2,%3}, [%4];"
                 : "=r"(r0), "=r"(r1), "=r"(r2), "=r"(r3) : "r"(addr));
}

__device__ __forceinline__ void mma_f32acc(float* d, const uint32_t* a,
                                           uint32_t b0, uint32_t b1) {
    asm volatile(
        "mma.sync.aligned.m16n8k16.row.col.f32.f16.f16.f32 "
        "{%0,%1,%2,%3}, {%4,%5,%6,%7}, {%8,%9}, {%0,%1,%2,%3};"
        : "+f"(d[0]), "+f"(d[1]), "+f"(d[2]), "+f"(d[3])
        : "r"(a[0]), "r"(a[1]), "r"(a[2]), "r"(a[3]), "r"(b0), "r"(b1));
}

__device__ __forceinline__ uint32_t pack_f16(float2 v) {
    uint32_t r;
    asm("cvt.rn.f16x2.f32 %0, %1, %2;" : "=r"(r) : "f"(v.y), "f"(v.x));
    return r;
}

__device__ __forceinline__ float softplus_lg2(float z) {
    // lg2(1 + 2^(z*log2e));  (softplus - ln2) = (this - 1) * ln2
    float w = z * LOG2E;
    float e, l;
    asm("ex2.approx.f32 %0, %1;" : "=f"(e) : "f"(w));
    asm("lg2.approx.f32 %0, %1;" : "=f"(l) : "f"(1.0f + e));
    return l;
}

// ---------------- prepped W1: fp16, transposed [j][k], padded stride --------

__device__ unsigned short g_wh[128 * WSTRIDE];

__global__ void prep_w1(const float* __restrict__ W1, float* __restrict__ out,
                        int out_n) {
    int idx = blockIdx.x * blockDim.x + threadIdx.x;
    if (idx < 128 * 128) {
        int j = idx >> 7;          // hidden (row of W^T)
        int k = idx & 127;         // contraction (contiguous)
        g_wh[j * WSTRIDE + k] = __half_as_ushort(__float2half_rn(W1[k * 128 + j]));
    }
    if (idx < out_n) out[idx] = 0.0f;
}

// ---------------- main persistent kernel ------------------------------------

__global__ void __launch_bounds__(NTHREADS, 1)
fused_mlp_hmma(const float* __restrict__ x,
               const float* __restrict__ b1,
               const float* __restrict__ W2,
               const int*   __restrict__ batch,
               float* __restrict__ out,
               int n_nodes, int n_tiles)
{
    extern __shared__ char dsm[];
    const uint32_t sbase = smem_u32(dsm);
    const uint32_t whb = sbase + OFF_W;

    __shared__ float s_b1[128];
    __shared__ float s_w2[128];              // W2 * ln2
    __shared__ float s_partial[2][2][64];    // [group][ngrp][node]

    const int tid  = threadIdx.x;
    const int wid  = tid >> 5;
    const int lane = tid & 31;
    const int g    = wid >> 2;         // group 0/1
    const int wg   = wid & 3;          // warp-in-group
    const int mgrp = wg & 1;           // 2 m-groups
    const int ngrp = wg >> 1;          // 2 n-groups x 64 hidden
    const int t128 = tid & 127;        // thread-in-group
    const int qr   = lane >> 2;
    const int qc   = lane & 3;

    const uint32_t xg = sbase + (uint32_t)g * (2 * XB64);

    // ---- prologue: stage W to smem, b1/w2 ---------------------------------
    {
        const uint4* gh = (const uint4*)g_wh;
        uint4* sh = (uint4*)(dsm + OFF_W);
        for (int i = tid; i < WBYTES / 16; i += NTHREADS)
            sh[i] = gh[i];
    }
    if (tid < 128) {
        s_b1[tid] = b1[tid];
        s_w2[tid] = W2[tid] * LN2;
    }
    __syncthreads();

    // per-thread constant: sum of w2*ln2 over this thread's 16 columns
    float c0 = 0.0f;
    #pragma unroll
    for (int nt = 0; nt < 8; nt++) {
        int jb = ngrp * 64 + nt * 8 + 2 * qc;
        c0 += s_w2[jb] + s_w2[jb + 1];
    }

    const int G2 = gridDim.x * 2;
    const int t0 = blockIdx.x * 2 + g;
    const int T = (t0 < n_tiles) ? ((n_tiles - 1 - t0) / G2 + 1) : 0;

    // ---- async x tile loader (64 rows, group-local) ------------------------
    auto load_tile = [&](int tile, int buf) {
        const float* src = x + (size_t)tile * TILE_M * 128;
        bool full = ((size_t)(tile + 1)) * TILE_M <= (size_t)n_nodes;
        #pragma unroll
        for (int it = 0; it < 16; it++) {
            int i = it * 128 + t128;
            int row = i >> 5;
            int ch  = i & 31;
            uint32_t dst = xg + (uint32_t)(buf * XB64 + row * (XSTRIDE * 4) + ch * 16);
            if (full || (size_t)tile * TILE_M + row < (size_t)n_nodes)
                cp_async16(dst, src + row * 128 + ch * 4);
            else
                sts_zero16(dst);
        }
        cp_commit();
    };

    // ---- compute one 64x128 tile ------------------------------------------
    auto compute_tile = [&](int tile, int buf) {
        float acc[2][8][4];
        #pragma unroll
        for (int mt = 0; mt < 2; mt++)
            #pragma unroll
            for (int nt = 0; nt < 8; nt++)
                #pragma unroll
                for (int e = 0; e < 4; e++) acc[mt][nt][e] = 0.0f;

        const uint32_t xb = xg + (uint32_t)buf * XB64;

        #pragma unroll 4
        for (int ks = 0; ks < 8; ks++) {
            const int k0 = ks * 16;
            const int kc = k0 + 2 * qc;

            // A fragments: fp32 from smem -> fp16 packs (one cvt per pair)
            uint32_t A[2][4];
            #pragma unroll
            for (int mt = 0; mt < 2; mt++) {
                int r = mt * 32 + (mgrp * 16) + qr;
                uint32_t b0 = xb + (uint32_t)((r * XSTRIDE + kc) * 4);
                A[mt][0] = pack_f16(lds64(b0));
                A[mt][1] = pack_f16(lds64(b0 + 8 * XSTRIDE * 4));
                A[mt][2] = pack_f16(lds64(b0 + 32));
                A[mt][3] = pack_f16(lds64(b0 + 8 * XSTRIDE * 4 + 32));
            }

            // B fragments + MMAs
            const uint32_t l8 = lane & 7;
            const uint32_t gsel = lane >> 3;
            #pragma unroll
            for (int ntp = 0; ntp < 4; ntp++) {
                uint32_t jrow = (uint32_t)(ngrp * 64 + ntp * 16) + ((gsel & 1) << 3) + l8;
                uint32_t kcol = (uint32_t)k0 + ((gsel >> 1) << 3);
                uint32_t off  = jrow * (WSTRIDE * 2) + kcol * 2;
                uint32_t h0, h1, h2, h3;
                ldmatrix_x4(h0, h1, h2, h3, whb + off);
                #pragma unroll
                for (int mt = 0; mt < 2; mt++) {
                    mma_f32acc(acc[mt][ntp * 2],     A[mt], h0, h2);
                    mma_f32acc(acc[mt][ntp * 2 + 1], A[mt], h1, h3);
                }
            }
        }

        // ---- epilogue: softplus + dot W2, lane reduce, node scatter -------
        float p[2][2];
        p[0][0] = p[0][1] = p[1][0] = p[1][1] = -c0;
        #pragma unroll
        for (int mt = 0; mt < 2; mt++) {
            #pragma unroll
            for (int nt = 0; nt < 8; nt++) {
                int jb = ngrp * 64 + nt * 8 + 2 * qc;
                float bx = s_b1[jb], by = s_b1[jb + 1];
                float wx = s_w2[jb], wy = s_w2[jb + 1];
                p[mt][0] = fmaf(softplus_lg2(acc[mt][nt][0] + bx), wx, p[mt][0]);
                p[mt][0] = fmaf(softplus_lg2(acc[mt][nt][1] + by), wy, p[mt][0]);
                p[mt][1] = fmaf(softplus_lg2(acc[mt][nt][2] + bx), wx, p[mt][1]);
                p[mt][1] = fmaf(softplus_lg2(acc[mt][nt][3] + by), wy, p[mt][1]);
            }
        }
        #pragma unroll
        for (int mt = 0; mt < 2; mt++)
            #pragma unroll
            for (int rr = 0; rr < 2; rr++) {
                p[mt][rr] += __shfl_xor_sync(0xffffffffu, p[mt][rr], 1);
                p[mt][rr] += __shfl_xor_sync(0xffffffffu, p[mt][rr], 2);
            }
        if (qc == 0) {
            #pragma unroll
            for (int mt = 0; mt < 2; mt++) {
                int nb = mt * 32 + mgrp * 16;
                s_partial[g][ngrp][nb + qr]     = p[mt][0];
                s_partial[g][ngrp][nb + qr + 8] = p[mt][1];
            }
        }
        group_bar(g);
        if (t128 < 64) {
            long gn = (long)tile * TILE_M + t128;
            if (gn < n_nodes) {
                float v = s_partial[g][0][t128] + s_partial[g][1][t128];
                atomicAdd(&out[batch[gn]], v);
            }
        }
        group_bar(g);   // protects s_partial and the x buffer being reloaded
    };

    // ---- pipeline ----------------------------------------------------------
    if (T > 0) {
        load_tile(t0, 0);
        for (int i = 0; i < T; i++) {
            if (i + 1 < T) {
                load_tile(t0 + (i + 1) * G2, (i + 1) & 1);
                asm volatile("cp.async.wait_group 1;" ::: "memory");
            } else {
                asm volatile("cp.async.wait_group 0;" ::: "memory");
            }
            group_bar(g);
            compute_tile(t0 + i * G2, i & 1);
        }
    }
}

// ---------------- launch -----------------------------------------------------

extern "C" void kernel_launch(void* const* d_in, const int* in_sizes, int n_in,
                              void* d_out, int out_size)
{
    const float* x     = (const float*)d_in[0];
    const float* W1    = (const float*)d_in[1];
    const float* b1    = (const float*)d_in[2];
    const float* W2    = (const float*)d_in[3];
    const int*   batch = (const int*)d_in[4];
    float* out = (float*)d_out;

    const int n_nodes = in_sizes[0] / 128;
    const int n_tiles = (n_nodes + TILE_M - 1) / TILE_M;

    prep_w1<<<64, 256>>>(W1, out, out_size);

    cudaFuncSetAttribute(fused_mlp_hmma,
                         cudaFuncAttributeMaxDynamicSharedMemorySize, SMEM_DYN);

    int sms = 148;
    cudaDeviceGetAttribute(&sms, cudaDevAttrMultiProcessorCount, 0);
    int pairs = (n_tiles + 1) / 2;
    int grid = (pairs < sms) ? pairs : sms;

    fused_mlp_hmma<<<grid, NTHREADS, SMEM_DYN>>>(x, b1, W2, batch, out,
                                                 n_nodes, n_tiles);
}

// round 8
// speedup vs baseline: 5.2386x; 1.0480x over previous
#include <cuda_runtime.h>
#include <cuda_fp16.h>
#include <cstdint>
#include <math.h>

// ============================================================================
// Fused Node2Prop2, mma.sync single-term fp16 (base sm_103 target).
//   H = fp16(X) @ fp16(W1), fp32 accum (rel_err ~5.7e-4, measured r7).
//   out[g] += sum_nodes ( softplus(H + b1) - ln2 ) @ W2
// Round 8: in-warp software pipelining — each warp overlaps tile i-1's
// MUFU/FMA epilogue with tile i's tensor-pipe MMAs (double accumulators),
// strength-reduced addressing, branch-free softplus (|z| small).
// ============================================================================

#define NTHREADS 256
#define TILE_M   64          // per-group tile rows

#define XSTRIDE  132         // fp32 floats per row (528B, 16B-aligned, shifted)
#define XB64     (64 * XSTRIDE * 4)           // 33792 per buffer
#define WSTRIDE  136         // halves per row (272B)
#define WBYTES   (128 * WSTRIDE * 2)          // 34816
#define OFF_W    (4 * XB64)                   // after 2 groups x 2 buffers
#define SMEM_DYN (4 * XB64 + WBYTES)          // 169984

#define LOG2E 1.4426950408889634f
#define LN2   0.6931471805599453f

// ---------------- helpers ---------------------------------------------------

__device__ __forceinline__ uint32_t smem_u32(const void* p) {
    uint32_t a;
    asm("{ .reg .u64 t; cvta.to.shared.u64 t, %1; cvt.u32.u64 %0, t; }"
        : "=r"(a) : "l"(p));
    return a;
}

__device__ __forceinline__ float2 lds64(uint32_t a) {
    float2 v;
    asm volatile("ld.shared.v2.f32 {%0, %1}, [%2];"
                 : "=f"(v.x), "=f"(v.y) : "r"(a));
    return v;
}

__device__ __forceinline__ void cp_async16(uint32_t dst, const float* src) {
    asm volatile("cp.async.cg.shared.global [%0], [%1], 16;"
                 :: "r"(dst), "l"(src) : "memory");
}
__device__ __forceinline__ void cp_commit() {
    asm volatile("cp.async.commit_group;" ::: "memory");
}
__device__ __forceinline__ void sts_zero16(uint32_t dst) {
    asm volatile("st.shared.v4.b32 [%0], {%1, %1, %1, %1};"
                 :: "r"(dst), "r"(0) : "memory");
}

__device__ __forceinline__ void group_bar(int g) {
    asm volatile("bar.sync %0, 128;" :: "r"(g + 1) : "memory");
}

__device__ __forceinline__ void ldmatrix_x4(uint32_t& r0, uint32_t& r1,
                                            uint32_t& r2, uint32_t& r3,
                                            uint32_t addr) {
    asm volatile("ldmatrix.sync.aligned.m8n8.x4.shared.b16 {%0,%1,%2,%3}, [%4];"
                 : "=r"(r0), "=r"(r1), "=r"(r2), "=r"(r3) : "r"(addr));
}

__device__ __forceinline__ void mma_f32acc(float* d, const uint32_t* a,
                                           uint32_t b0, uint32_t b1) {
    asm volatile(
        "mma.sync.aligned.m16n8k16.row.col.f32.f16.f16.f32 "
        "{%0,%1,%2,%3}, {%4,%5,%6,%7}, {%8,%9}, {%0,%1,%2,%3};"
        : "+f"(d[0]), "+f"(d[1]), "+f"(d[2]), "+f"(d[3])
        : "r"(a[0]), "r"(a[1]), "r"(a[2]), "r"(a[3]), "r"(b0), "r"(b1));
}

__device__ __forceinline__ uint32_t pack_f16(float2 v) {
    uint32_t r;
    asm("cvt.rn.f16x2.f32 %0, %1, %2;" : "=r"(r) : "f"(v.y), "f"(v.x));
    return r;
}

// branch-free: z = acc + b1.  p += (softplus(z)-ln2)*w2, with the -ln2*w2
// constant hoisted into p's init.  Needs: w = acc*log2e + b1*log2e (1 FMA),
// e = 2^w, l = lg2(1+e), p += l * (w2*ln2).  Safe: |z| <= ~15 here.
__device__ __forceinline__ void sp_acc(float& p, float acc, float bl2, float w2l2) {
    float w = fmaf(acc, LOG2E, bl2);
    float e, l;
    asm("ex2.approx.f32 %0, %1;" : "=f"(e) : "f"(w));
    asm("lg2.approx.f32 %0, %1;" : "=f"(l) : "f"(1.0f + e));
    p = fmaf(l, w2l2, p);
}

// ---------------- prepped W1: fp16, transposed [j][k], padded stride --------

__device__ unsigned short g_wh[128 * WSTRIDE];

__global__ void prep_w1(const float* __restrict__ W1, float* __restrict__ out,
                        int out_n) {
    int idx = blockIdx.x * blockDim.x + threadIdx.x;
    if (idx < 128 * 128) {
        int j = idx >> 7;
        int k = idx & 127;
        g_wh[j * WSTRIDE + k] = __half_as_ushort(__float2half_rn(W1[k * 128 + j]));
    }
    if (idx < out_n) out[idx] = 0.0f;
}

// ---------------- main persistent kernel ------------------------------------

__global__ void __launch_bounds__(NTHREADS, 1)
fused_mlp_hmma(const float* __restrict__ x,
               const float* __restrict__ b1,
               const float* __restrict__ W2,
               const int*   __restrict__ batch,
               float* __restrict__ out,
               int n_nodes, int n_tiles)
{
    extern __shared__ char dsm[];
    const uint32_t sbase = smem_u32(dsm);
    const uint32_t whb = sbase + OFF_W;

    __shared__ float s_b1l2[128];            // b1 * log2e
    __shared__ float s_w2l2[128];            // W2 * ln2
    __shared__ float s_partial[2][2][64];    // [group][ngrp][node]

    const int tid  = threadIdx.x;
    const int wid  = tid >> 5;
    const int lane = tid & 31;
    const int g    = wid >> 2;         // group 0/1
    const int wg   = wid & 3;          // warp-in-group
    const int mgrp = wg & 1;
    const int ngrp = wg >> 1;          // 2 n-groups x 64 hidden
    const int t128 = tid & 127;
    const int qr   = lane >> 2;
    const int qc   = lane & 3;

    const uint32_t xg = sbase + (uint32_t)g * (2 * XB64);

    // ---- prologue ---------------------------------------------------------
    {
        const uint4* gh = (const uint4*)g_wh;
        uint4* sh = (uint4*)(dsm + OFF_W);
        for (int i = tid; i < WBYTES / 16; i += NTHREADS)
            sh[i] = gh[i];
    }
    if (tid < 128) {
        s_b1l2[tid] = b1[tid] * LOG2E;
        s_w2l2[tid] = W2[tid] * LN2;
    }
    __syncthreads();

    // per-thread bias/weight registers for this thread's 16 columns
    float lb[8][2], lw[8][2];
    float c0 = 0.0f;
    #pragma unroll
    for (int nt = 0; nt < 8; nt++) {
        int jb = ngrp * 64 + nt * 8 + 2 * qc;
        lb[nt][0] = s_b1l2[jb];     lb[nt][1] = s_b1l2[jb + 1];
        lw[nt][0] = s_w2l2[jb];     lw[nt][1] = s_w2l2[jb + 1];
        c0 += lw[nt][0] + lw[nt][1];
    }

    const int G2 = gridDim.x * 2;
    const int t0 = blockIdx.x * 2 + g;
    const int T = (t0 < n_tiles) ? ((n_tiles - 1 - t0) / G2 + 1) : 0;

    // B base addresses per ntp (loop-invariant across tiles and ks)
    uint32_t bbase[4];
    {
        const uint32_t l8 = lane & 7;
        const uint32_t gsel = lane >> 3;
        #pragma unroll
        for (int ntp = 0; ntp < 4; ntp++) {
            uint32_t jrow = (uint32_t)(ngrp * 64 + ntp * 16) + ((gsel & 1) << 3) + l8;
            bbase[ntp] = whb + jrow * (WSTRIDE * 2) + (((gsel >> 1) << 3) << 1);
        }
    }
    // A base addresses within a buffer (add buf*XB64 at use)
    const uint32_t arow0 = (uint32_t)(((mgrp * 16 + qr) * XSTRIDE + 2 * qc) * 4);
    const uint32_t arow1 = arow0 + 32 * XSTRIDE * 4;

    // ---- async x tile loader ----------------------------------------------
    auto load_tile = [&](int tile, int buf) {
        const float* src = x + (size_t)tile * TILE_M * 128;
        bool full = ((size_t)(tile + 1)) * TILE_M <= (size_t)n_nodes;
        #pragma unroll
        for (int it = 0; it < 16; it++) {
            int i = it * 128 + t128;
            int row = i >> 5;
            int ch  = i & 31;
            uint32_t dst = xg + (uint32_t)(buf * XB64 + row * (XSTRIDE * 4) + ch * 16);
            if (full || (size_t)tile * TILE_M + row < (size_t)n_nodes)
                cp_async16(dst, src + row * 128 + ch * 4);
            else
                sts_zero16(dst);
        }
        cp_commit();
    };

    // ---- fused: MMA of current tile + epilogue chunks of previous ---------
    // aN: accumulators to fill; aP: previous tile's accumulators (consumed
    // when doEpi). p[2][2] receives the previous tile's partial dot-products.
    auto fused = [&](int buf, float (&aN)[2][8][4], float (&aP)[2][8][4],
                     bool doEpi, float (&p)[2][2]) {
        #pragma unroll
        for (int mt = 0; mt < 2; mt++)
            #pragma unroll
            for (int nt = 0; nt < 8; nt++)
                #pragma unroll
                for (int e = 0; e < 4; e++) aN[mt][nt][e] = 0.0f;
        p[0][0] = p[0][1] = p[1][0] = p[1][1] = -c0;

        const uint32_t x0 = xg + (uint32_t)buf * XB64 + arow0;
        const uint32_t x1 = xg + (uint32_t)buf * XB64 + arow1;

        #pragma unroll
        for (int ks = 0; ks < 8; ks++) {
            const uint32_t ko = (uint32_t)(ks * 64);   // 16 floats = 64B
            uint32_t A0[4], A1[4];
            A0[0] = pack_f16(lds64(x0 + ko));
            A0[1] = pack_f16(lds64(x0 + ko + 8 * XSTRIDE * 4));
            A0[2] = pack_f16(lds64(x0 + ko + 32));
            A0[3] = pack_f16(lds64(x0 + ko + 8 * XSTRIDE * 4 + 32));
            A1[0] = pack_f16(lds64(x1 + ko));
            A1[1] = pack_f16(lds64(x1 + ko + 8 * XSTRIDE * 4));
            A1[2] = pack_f16(lds64(x1 + ko + 32));
            A1[3] = pack_f16(lds64(x1 + ko + 8 * XSTRIDE * 4 + 32));

            #pragma unroll
            for (int ntp = 0; ntp < 4; ntp++) {
                uint32_t h0, h1, h2, h3;
                ldmatrix_x4(h0, h1, h2, h3, bbase[ntp] + (uint32_t)(ks * 32));
                mma_f32acc(aN[0][ntp * 2],     A0, h0, h2);
                mma_f32acc(aN[0][ntp * 2 + 1], A0, h1, h3);
                mma_f32acc(aN[1][ntp * 2],     A1, h0, h2);
                mma_f32acc(aN[1][ntp * 2 + 1], A1, h1, h3);
            }

            if (doEpi) {
                // epilogue chunk: nt = ks of the previous tile (MUFU/FMA pipes,
                // overlaps the tensor-pipe MMAs above)
                #pragma unroll
                for (int mt = 0; mt < 2; mt++) {
                    sp_acc(p[mt][0], aP[mt][ks][0], lb[ks][0], lw[ks][0]);
                    sp_acc(p[mt][0], aP[mt][ks][1], lb[ks][1], lw[ks][1]);
                    sp_acc(p[mt][1], aP[mt][ks][2], lb[ks][0], lw[ks][0]);
                    sp_acc(p[mt][1], aP[mt][ks][3], lb[ks][1], lw[ks][1]);
                }
            }
        }
    };

    // ---- epilogue-only (drain for the final tile) --------------------------
    auto epi_only = [&](float (&aP)[2][8][4], float (&p)[2][2]) {
        p[0][0] = p[0][1] = p[1][0] = p[1][1] = -c0;
        #pragma unroll
        for (int nt = 0; nt < 8; nt++)
            #pragma unroll
            for (int mt = 0; mt < 2; mt++) {
                sp_acc(p[mt][0], aP[mt][nt][0], lb[nt][0], lw[nt][0]);
                sp_acc(p[mt][0], aP[mt][nt][1], lb[nt][1], lw[nt][1]);
                sp_acc(p[mt][1], aP[mt][nt][2], lb[nt][0], lw[nt][0]);
                sp_acc(p[mt][1], aP[mt][nt][3], lb[nt][1], lw[nt][1]);
            }
    };

    // ---- reduce p across quad lanes, stage, scatter (for tile 'tile') -----
    auto scatter = [&](float (&p)[2][2], int tile) {
        #pragma unroll
        for (int mt = 0; mt < 2; mt++)
            #pragma unroll
            for (int rr = 0; rr < 2; rr++) {
                p[mt][rr] += __shfl_xor_sync(0xffffffffu, p[mt][rr], 1);
                p[mt][rr] += __shfl_xor_sync(0xffffffffu, p[mt][rr], 2);
            }
        if (qc == 0) {
            #pragma unroll
            for (int mt = 0; mt < 2; mt++) {
                int nb = mt * 32 + mgrp * 16;
                s_partial[g][ngrp][nb + qr]     = p[mt][0];
                s_partial[g][ngrp][nb + qr + 8] = p[mt][1];
            }
        }
        group_bar(g);
        if (t128 < 64) {
            long gn = (long)tile * TILE_M + t128;
            if (gn < n_nodes) {
                float v = s_partial[g][0][t128] + s_partial[g][1][t128];
                atomicAdd(&out[batch[gn]], v);
            }
        }
    };

    // ---- pipeline ----------------------------------------------------------
    float accA[2][8][4], accB[2][8][4];

    if (T > 0) {
        load_tile(t0, 0);
        for (int i = 0; i < T; i++) {
            if (i + 1 < T) {
                load_tile(t0 + (i + 1) * G2, (i + 1) & 1);
                asm volatile("cp.async.wait_group 1;" ::: "memory");
            } else {
                asm volatile("cp.async.wait_group 0;" ::: "memory");
            }
            group_bar(g);          // buffer i ready for all warps
            float p[2][2];
            if (i & 1) fused(i & 1, accB, accA, i > 0, p);
            else       fused(i & 1, accA, accB, i > 0, p);
            if (i > 0) scatter(p, t0 + (i - 1) * G2);
            group_bar(g);          // all MMA reads + s_partial reads done
        }
        // drain: epilogue of the last tile
        float p[2][2];
        if (T & 1) epi_only(accA, p);   // last written set: even i -> accA
        else       epi_only(accB, p);
        scatter(p, t0 + (T - 1) * G2);
    }
}

// ---------------- launch -----------------------------------------------------

extern "C" void kernel_launch(void* const* d_in, const int* in_sizes, int n_in,
                              void* d_out, int out_size)
{
    const float* x     = (const float*)d_in[0];
    const float* W1    = (const float*)d_in[1];
    const float* b1    = (const float*)d_in[2];
    const float* W2    = (const float*)d_in[3];
    const int*   batch = (const int*)d_in[4];
    float* out = (float*)d_out;

    const int n_nodes = in_sizes[0] / 128;
    const int n_tiles = (n_nodes + TILE_M - 1) / TILE_M;

    prep_w1<<<64, 256>>>(W1, out, out_size);

    cudaFuncSetAttribute(fused_mlp_hmma,
                         cudaFuncAttributeMaxDynamicSharedMemorySize, SMEM_DYN);

    int sms = 148;
    cudaDeviceGetAttribute(&sms, cudaDevAttrMultiProcessorCount, 0);
    int pairs = (n_tiles + 1) / 2;
    int grid = (pairs < sms) ? pairs : sms;

    fused_mlp_hmma<<<grid, NTHREADS, SMEM_DYN>>>(x, b1, W2, batch, out,
                                                 n_nodes, n_tiles);
}